// round 1
// baseline (speedup 1.0000x reference)
#include <cuda_runtime.h>
#include <cuda_bf16.h>

#define BATCH 2
#define CH 64
#define HW 4096   // 64*64

// ---------------- scratch (device globals; no allocation allowed) ----------------
__device__ float g_scale[4 * CH];
__device__ float g_xg[BATCH * CH * HW];
__device__ float g_gg[BATCH * CH * HW];
__device__ float g_xq[BATCH * CH * HW];
__device__ float g_xk[BATCH * CH * HW];
__device__ float g_xv[BATCH * CH * HW];
__device__ float g_gq[BATCH * CH * HW];
__device__ float g_gk[BATCH * CH * HW];
__device__ float g_xout[BATCH * CH * HW];
__device__ float g_gout[BATCH * CH * HW];
__device__ float g_outb[BATCH * CH * HW];
__device__ float g_t1[BATCH * CH * HW];
__device__ float g_t2[BATCH * CH * HW];
__device__ float g_sc[BATCH * CH * HW];

#define BUF_XG 0
#define BUF_GG 1
#define BUF_OUT 2
#define BUF_T1 3

#define BUF_XQ 0
#define BUF_XK 1
#define BUF_XV 2
#define BUF_GQ 3
#define BUF_GK 4
#define BUF_SC 5
#define BUF_OT1 6
#define BUF_OT2 7

__device__ __forceinline__ float* pick_in(int w) {
    switch (w) {
        case BUF_XG: return g_xg;
        case BUF_GG: return g_gg;
        case BUF_OUT: return g_outb;
        default:     return g_t1;
    }
}
__device__ __forceinline__ float* pick_out(int w) {
    switch (w) {
        case BUF_XQ: return g_xq;
        case BUF_XK: return g_xk;
        case BUF_XV: return g_xv;
        case BUF_GQ: return g_gq;
        case BUF_GK: return g_gk;
        case BUF_SC: return g_sc;
        case BUF_OT1: return g_t1;
        default:      return g_t2;
    }
}

// ---------------- 1. channel attention scalars ----------------
__global__ void kstats(const float* __restrict__ x, const float* __restrict__ g,
                       const float* __restrict__ lw, const float* __restrict__ lb) {
    int idx = blockIdx.x;
    int t = idx >> 7, b = (idx >> 6) & 1, c = idx & 63;
    const float* in = (t ? g : x) + (b * CH + c) * HW;
    float s = 0.f;
    for (int i = threadIdx.x; i < HW; i += 256) s += in[i];
    __shared__ float red[8];
    #pragma unroll
    for (int o = 16; o > 0; o >>= 1) s += __shfl_xor_sync(0xffffffffu, s, o);
    if ((threadIdx.x & 31) == 0) red[threadIdx.x >> 5] = s;
    __syncthreads();
    if (threadIdx.x == 0) {
        float tot = 0.f;
        #pragma unroll
        for (int i = 0; i < 8; i++) tot += red[i];
        float p = tot * (1.0f / (float)HW);
        float W = lw[0], B = lb[0];
        float h = p * W + B;
        h = h > 0.f ? h : 0.1f * h;
        float z = h * W + B;
        g_scale[idx] = 1.f / (1.f + expf(-z));
    }
}

// ---------------- 2. gated coord conv ----------------
__global__ void kgated(const float* __restrict__ xin, const float* __restrict__ gin,
                       const float* __restrict__ cw) {
    int z = blockIdx.z;
    int t = z >> 1, b = z & 1;
    const float* in = (t ? gin : xin) + b * CH * HW;
    float* out = (t ? g_gg : g_xg) + b * CH * HW;
    int oc = blockIdx.y;

    __shared__ float ws[66 * 9];
    for (int i = threadIdx.x; i < 66 * 9; i += 256) ws[i] = cw[oc * (66 * 9) + i];
    __syncthreads();

    int p = blockIdx.x * 1024 + threadIdx.x * 4;
    int row = p >> 6, col0 = p & 63;
    float acc[4] = {0.f, 0.f, 0.f, 0.f};

    for (int ic = 0; ic < 64; ic++) {
        const float* ch = in + ic * HW;
        #pragma unroll
        for (int kh = 0; kh < 3; kh++) {
            int hh = row + kh - 1;
            if ((unsigned)hh >= 64u) continue;
            float v[6];
            #pragma unroll
            for (int u = 0; u < 6; u++) {
                int cc = col0 - 1 + u;
                v[u] = ((unsigned)cc < 64u) ? ch[hh * 64 + cc] : 0.f;
            }
            const float* wr = &ws[ic * 9 + kh * 3];
            #pragma unroll
            for (int kw = 0; kw < 3; kw++) {
                float wv = wr[kw];
                acc[0] += wv * v[kw + 0];
                acc[1] += wv * v[kw + 1];
                acc[2] += wv * v[kw + 2];
                acc[3] += wv * v[kw + 3];
            }
        }
    }
    #pragma unroll
    for (int ic = 64; ic < 66; ic++) {
        #pragma unroll
        for (int kh = 0; kh < 3; kh++) {
            int hh = row + kh - 1;
            if ((unsigned)hh >= 64u) continue;
            float yyv = (float)hh * (2.f / 63.f) - 1.f;
            float v[6];
            #pragma unroll
            for (int u = 0; u < 6; u++) {
                int cc = col0 - 1 + u;
                float val = 0.f;
                if ((unsigned)cc < 64u)
                    val = (ic == 64) ? ((float)cc * (2.f / 63.f) - 1.f) : yyv;
                v[u] = val;
            }
            const float* wr = &ws[ic * 9 + kh * 3];
            #pragma unroll
            for (int kw = 0; kw < 3; kw++) {
                float wv = wr[kw];
                acc[0] += wv * v[kw + 0];
                acc[1] += wv * v[kw + 1];
                acc[2] += wv * v[kw + 2];
                acc[3] += wv * v[kw + 3];
            }
        }
    }

    float s = g_scale[z * CH + oc];
    float* op = out + oc * HW + p;
    op[0] = s * acc[0];
    op[1] = s * acc[1];
    op[2] = s * acc[2];
    op[3] = s * acc[3];
}

// ---------------- 3. 1x1 conv ----------------
__global__ void k1x1(const float* __restrict__ w, const float* __restrict__ bias,
                     int in_id, int out_id) {
    const float* in = pick_in(in_id);
    float* out = pick_out(out_id);
    int b = blockIdx.z, og = blockIdx.y;
    int n0 = blockIdx.x * 128;

    __shared__ float si[64 * 128];
    __shared__ float sw[8 * 64];
    for (int i = threadIdx.x; i < 64 * 128; i += 128) {
        int c = i >> 7, px = i & 127;
        si[i] = in[(b * CH + c) * HW + n0 + px];
    }
    for (int i = threadIdx.x; i < 512; i += 128)
        sw[i] = w[(og * 8 + (i >> 6)) * 64 + (i & 63)];
    __syncthreads();

    float acc[8];
    #pragma unroll
    for (int o = 0; o < 8; o++) acc[o] = bias[og * 8 + o];
    for (int c = 0; c < 64; c++) {
        float iv = si[c * 128 + threadIdx.x];
        #pragma unroll
        for (int o = 0; o < 8; o++) acc[o] += sw[o * 64 + c] * iv;
    }
    #pragma unroll
    for (int o = 0; o < 8; o++)
        out[(b * CH + og * 8 + o) * HW + n0 + threadIdx.x] = acc[o];
}

// ---------------- 4. flash attention ----------------
__global__ void kflash() {
    extern __shared__ float sm[];
    float* Qs = sm;               // [64][64]
    float* Ks = Qs + 64 * 64;     // [64][64]
    float* Vs = Ks + 64 * 64;     // [64][65]
    float* Ps = Vs + 64 * 65;     // [64][65]

    int b = blockIdx.y, kind = blockIdx.z;
    int n0 = blockIdx.x * 64;
    const float* Q = (kind ? g_gq : g_xq) + b * CH * HW;
    const float* K = (kind ? g_gk : g_xk) + b * CH * HW;
    const float* V = g_xv + b * CH * HW;
    float* O = (kind ? g_gout : g_xout) + b * CH * HW;

    int tid = threadIdx.x;
    int tx = tid & 15, ty = tid >> 4;

    for (int i = tid; i < 4096; i += 256) {
        int c = i >> 6, n = i & 63;
        Qs[c * 64 + n] = Q[c * HW + n0 + n];
    }

    float o[4][4];
    float m[4], l[4];
    #pragma unroll
    for (int ii = 0; ii < 4; ii++) {
        m[ii] = -1e30f; l[ii] = 0.f;
        #pragma unroll
        for (int s2 = 0; s2 < 4; s2++) o[ii][s2] = 0.f;
    }

    for (int kt = 0; kt < 64; kt++) {
        int m0 = kt * 64;
        __syncthreads();
        for (int i = tid; i < 4096; i += 256) {
            int c = i >> 6, n = i & 63;
            Ks[c * 64 + n] = K[c * HW + m0 + n];
            Vs[c * 65 + n] = V[c * HW + m0 + n];
        }
        __syncthreads();

        float s[4][4];
        #pragma unroll
        for (int ii = 0; ii < 4; ii++)
            #pragma unroll
            for (int jj = 0; jj < 4; jj++) s[ii][jj] = 0.f;

        #pragma unroll 4
        for (int c = 0; c < 64; c++) {
            float4 a4 = *(const float4*)(Qs + c * 64 + 4 * ty);
            float4 b4 = *(const float4*)(Ks + c * 64 + 4 * tx);
            float a[4] = {a4.x, a4.y, a4.z, a4.w};
            float bb[4] = {b4.x, b4.y, b4.z, b4.w};
            #pragma unroll
            for (int ii = 0; ii < 4; ii++)
                #pragma unroll
                for (int jj = 0; jj < 4; jj++) s[ii][jj] += a[ii] * bb[jj];
        }

        #pragma unroll
        for (int ii = 0; ii < 4; ii++) {
            float tm = fmaxf(fmaxf(s[ii][0], s[ii][1]), fmaxf(s[ii][2], s[ii][3]));
            #pragma unroll
            for (int off = 1; off < 16; off <<= 1)
                tm = fmaxf(tm, __shfl_xor_sync(0xffffffffu, tm, off));
            float mn = fmaxf(m[ii], tm);
            float p[4], ps = 0.f;
            #pragma unroll
            for (int jj = 0; jj < 4; jj++) { p[jj] = __expf(s[ii][jj] - mn); ps += p[jj]; }
            #pragma unroll
            for (int off = 1; off < 16; off <<= 1)
                ps += __shfl_xor_sync(0xffffffffu, ps, off);
            float corr = __expf(m[ii] - mn);
            l[ii] = l[ii] * corr + ps;
            m[ii] = mn;
            #pragma unroll
            for (int s2 = 0; s2 < 4; s2++) o[ii][s2] *= corr;
            #pragma unroll
            for (int jj = 0; jj < 4; jj++)
                Ps[(4 * ty + ii) * 65 + 4 * tx + jj] = p[jj];
        }
        __syncthreads();

        #pragma unroll 2
        for (int j = 0; j < 64; j++) {
            float vv[4];
            #pragma unroll
            for (int s2 = 0; s2 < 4; s2++) vv[s2] = Vs[(4 * tx + s2) * 65 + j];
            #pragma unroll
            for (int ii = 0; ii < 4; ii++) {
                float pv = Ps[(4 * ty + ii) * 65 + j];
                #pragma unroll
                for (int s2 = 0; s2 < 4; s2++) o[ii][s2] += pv * vv[s2];
            }
        }
    }

    #pragma unroll
    for (int ii = 0; ii < 4; ii++) {
        float inv = 1.f / l[ii];
        int i = 4 * ty + ii;
        #pragma unroll
        for (int s2 = 0; s2 < 4; s2++) {
            int c = 4 * tx + s2;
            O[c * HW + n0 + i] = o[ii][s2] * inv;
        }
    }
}

// ---------------- 5. combine ----------------
__global__ void kcombine(const float* __restrict__ gamma, const float* __restrict__ alpha) {
    int i = blockIdx.x * 256 + threadIdx.x;
    g_outb[i] = gamma[0] * g_xout[i] + alpha[0] * g_gout[i];
}

// ---------------- 6. plain conv3x3 ----------------
__global__ void kconv3(const float* __restrict__ w, const float* __restrict__ bias,
                       int in_id, int out_id, int leaky_in) {
    const float* inb = pick_in(in_id);
    float* outb = pick_out(out_id);
    int b = blockIdx.z, oc = blockIdx.y;

    __shared__ float ws[576];
    for (int i = threadIdx.x; i < 576; i += 256) ws[i] = w[oc * 576 + i];
    __syncthreads();

    int p = blockIdx.x * 1024 + threadIdx.x * 4;
    int row = p >> 6, col0 = p & 63;
    float bv = bias[oc];
    float acc[4] = {bv, bv, bv, bv};
    const float* in = inb + b * CH * HW;

    for (int ic = 0; ic < 64; ic++) {
        const float* ch = in + ic * HW;
        #pragma unroll
        for (int kh = 0; kh < 3; kh++) {
            int hh = row + kh - 1;
            if ((unsigned)hh >= 64u) continue;
            float v[6];
            #pragma unroll
            for (int u = 0; u < 6; u++) {
                int cc = col0 - 1 + u;
                float val = ((unsigned)cc < 64u) ? ch[hh * 64 + cc] : 0.f;
                if (leaky_in) val = val > 0.f ? val : 0.1f * val;
                v[u] = val;
            }
            const float* wr = &ws[ic * 9 + kh * 3];
            #pragma unroll
            for (int kw = 0; kw < 3; kw++) {
                float wv = wr[kw];
                acc[0] += wv * v[kw + 0];
                acc[1] += wv * v[kw + 1];
                acc[2] += wv * v[kw + 2];
                acc[3] += wv * v[kw + 3];
            }
        }
    }
    float* op = outb + (b * CH + oc) * HW + p;
    op[0] = acc[0]; op[1] = acc[1]; op[2] = acc[2]; op[3] = acc[3];
}

// ---------------- 7. final ----------------
__global__ void kfinal(float* __restrict__ dout) {
    int i = blockIdx.x * 256 + threadIdx.x;
    dout[i] = g_t2[i] + g_sc[i] * g_gout[i];
}

extern "C" void kernel_launch(void* const* d_in, const int* in_sizes, int n_in,
                              void* d_out, int out_size) {
    const float* x       = (const float*)d_in[0];
    const float* guide   = (const float*)d_in[1];
    const float* lin_w   = (const float*)d_in[2];
    const float* lin_b   = (const float*)d_in[3];
    const float* coord_w = (const float*)d_in[4];
    const float* xq_w = (const float*)d_in[5];
    const float* xq_b = (const float*)d_in[6];
    const float* xk_w = (const float*)d_in[7];
    const float* xk_b = (const float*)d_in[8];
    const float* xv_w = (const float*)d_in[9];
    const float* xv_b = (const float*)d_in[10];
    const float* gq_w = (const float*)d_in[11];
    const float* gq_b = (const float*)d_in[12];
    const float* gk_w = (const float*)d_in[13];
    const float* gk_b = (const float*)d_in[14];
    const float* gamma = (const float*)d_in[15];
    const float* alpha = (const float*)d_in[16];
    const float* c1_w = (const float*)d_in[17];
    const float* c1_b = (const float*)d_in[18];
    const float* c2_w = (const float*)d_in[19];
    const float* c2_b = (const float*)d_in[20];
    const float* sc_w = (const float*)d_in[21];
    const float* sc_b = (const float*)d_in[22];
    float* out = (float*)d_out;

    cudaFuncSetAttribute(kflash, cudaFuncAttributeMaxDynamicSharedMemorySize, 66048);

    kstats<<<256, 256>>>(x, guide, lin_w, lin_b);
    kgated<<<dim3(4, 64, 4), 256>>>(x, guide, coord_w);

    k1x1<<<dim3(32, 8, BATCH), 128>>>(xq_w, xq_b, BUF_XG, BUF_XQ);
    k1x1<<<dim3(32, 8, BATCH), 128>>>(xk_w, xk_b, BUF_XG, BUF_XK);
    k1x1<<<dim3(32, 8, BATCH), 128>>>(xv_w, xv_b, BUF_XG, BUF_XV);
    k1x1<<<dim3(32, 8, BATCH), 128>>>(gq_w, gq_b, BUF_GG, BUF_GQ);
    k1x1<<<dim3(32, 8, BATCH), 128>>>(gk_w, gk_b, BUF_GG, BUF_GK);

    kflash<<<dim3(64, BATCH, 2), 256, 66048>>>();

    kcombine<<<2048, 256>>>(gamma, alpha);

    kconv3<<<dim3(4, 64, BATCH), 256>>>(c1_w, c1_b, BUF_OUT, BUF_OT1, 1);
    kconv3<<<dim3(4, 64, BATCH), 256>>>(c2_w, c2_b, BUF_T1, BUF_OT2, 1);

    k1x1<<<dim3(32, 8, BATCH), 128>>>(sc_w, sc_b, BUF_OUT, BUF_SC);

    kfinal<<<2048, 256>>>(out);
}

// round 2
// speedup vs baseline: 1.1721x; 1.1721x over previous
#include <cuda_runtime.h>
#include <cuda_bf16.h>

#define BATCH 2
#define CH 64
#define HW 4096   // 64*64

typedef unsigned long long u64;

__device__ __forceinline__ u64 pk2(float lo, float hi) {
    u64 r; asm("mov.b64 %0,{%1,%2};" : "=l"(r) : "f"(lo), "f"(hi)); return r;
}
__device__ __forceinline__ void upk2(u64 v, float& lo, float& hi) {
    asm("mov.b64 {%0,%1},%2;" : "=f"(lo), "=f"(hi) : "l"(v));
}
__device__ __forceinline__ u64 ffma2(u64 a, u64 b, u64 c) {
    u64 d; asm("fma.rn.f32x2 %0,%1,%2,%3;" : "=l"(d) : "l"(a), "l"(b), "l"(c)); return d;
}
__device__ __forceinline__ u64 fmul2(u64 a, u64 b) {
    u64 d; asm("mul.rn.f32x2 %0,%1,%2;" : "=l"(d) : "l"(a), "l"(b)); return d;
}

// ---------------- scratch ----------------
__device__ float g_scale[4 * CH];
__device__ float g_xg[BATCH * CH * HW];
__device__ float g_gg[BATCH * CH * HW];
__device__ float g_xq[BATCH * CH * HW];
__device__ float g_xk[BATCH * CH * HW];
__device__ float g_xv[BATCH * CH * HW];
__device__ float g_gq[BATCH * CH * HW];
__device__ float g_gk[BATCH * CH * HW];
__device__ float g_xout[BATCH * CH * HW];
__device__ float g_gout[BATCH * CH * HW];
__device__ float g_outb[BATCH * CH * HW];
__device__ float g_t1[BATCH * CH * HW];
__device__ float g_t2[BATCH * CH * HW];
__device__ float g_sc[BATCH * CH * HW];

#define BUF_XG 0
#define BUF_GG 1
#define BUF_OUT 2
#define BUF_T1 3

#define BUF_XQ 0
#define BUF_XK 1
#define BUF_XV 2
#define BUF_GQ 3
#define BUF_GK 4
#define BUF_SC 5
#define BUF_OT1 6
#define BUF_OT2 7

__device__ __forceinline__ float* pick_in(int w) {
    switch (w) {
        case BUF_XG: return g_xg;
        case BUF_GG: return g_gg;
        case BUF_OUT: return g_outb;
        default:     return g_t1;
    }
}
__device__ __forceinline__ float* pick_out(int w) {
    switch (w) {
        case BUF_XQ: return g_xq;
        case BUF_XK: return g_xk;
        case BUF_XV: return g_xv;
        case BUF_GQ: return g_gq;
        case BUF_GK: return g_gk;
        case BUF_SC: return g_sc;
        case BUF_OT1: return g_t1;
        default:      return g_t2;
    }
}

// ---------------- 1. channel attention scalars ----------------
__global__ void kstats(const float* __restrict__ x, const float* __restrict__ g,
                       const float* __restrict__ lw, const float* __restrict__ lb) {
    int idx = blockIdx.x;
    int t = idx >> 7, b = (idx >> 6) & 1, c = idx & 63;
    const float* in = (t ? g : x) + (b * CH + c) * HW;
    float s = 0.f;
    for (int i = threadIdx.x; i < HW; i += 256) s += in[i];
    __shared__ float red[8];
    #pragma unroll
    for (int o = 16; o > 0; o >>= 1) s += __shfl_xor_sync(0xffffffffu, s, o);
    if ((threadIdx.x & 31) == 0) red[threadIdx.x >> 5] = s;
    __syncthreads();
    if (threadIdx.x == 0) {
        float tot = 0.f;
        #pragma unroll
        for (int i = 0; i < 8; i++) tot += red[i];
        float p = tot * (1.0f / (float)HW);
        float W = lw[0], B = lb[0];
        float h = p * W + B;
        h = h > 0.f ? h : 0.1f * h;
        float z = h * W + B;
        g_scale[idx] = 1.f / (1.f + expf(-z));
    }
}

// ---------------- 2. gated coord conv ----------------
__global__ void kgated(const float* __restrict__ xin, const float* __restrict__ gin,
                       const float* __restrict__ cw) {
    int z = blockIdx.z;
    int t = z >> 1, b = z & 1;
    const float* in = (t ? gin : xin) + b * CH * HW;
    float* out = (t ? g_gg : g_xg) + b * CH * HW;
    int oc = blockIdx.y;

    __shared__ float ws[66 * 9];
    for (int i = threadIdx.x; i < 66 * 9; i += 256) ws[i] = cw[oc * (66 * 9) + i];
    __syncthreads();

    int p = blockIdx.x * 1024 + threadIdx.x * 4;
    int row = p >> 6, col0 = p & 63;
    float acc[4] = {0.f, 0.f, 0.f, 0.f};

    for (int ic = 0; ic < 64; ic++) {
        const float* ch = in + ic * HW;
        #pragma unroll
        for (int kh = 0; kh < 3; kh++) {
            int hh = row + kh - 1;
            if ((unsigned)hh >= 64u) continue;
            float v[6];
            #pragma unroll
            for (int u = 0; u < 6; u++) {
                int cc = col0 - 1 + u;
                v[u] = ((unsigned)cc < 64u) ? ch[hh * 64 + cc] : 0.f;
            }
            const float* wr = &ws[ic * 9 + kh * 3];
            #pragma unroll
            for (int kw = 0; kw < 3; kw++) {
                float wv = wr[kw];
                acc[0] += wv * v[kw + 0];
                acc[1] += wv * v[kw + 1];
                acc[2] += wv * v[kw + 2];
                acc[3] += wv * v[kw + 3];
            }
        }
    }
    #pragma unroll
    for (int ic = 64; ic < 66; ic++) {
        #pragma unroll
        for (int kh = 0; kh < 3; kh++) {
            int hh = row + kh - 1;
            if ((unsigned)hh >= 64u) continue;
            float yyv = (float)hh * (2.f / 63.f) - 1.f;
            float v[6];
            #pragma unroll
            for (int u = 0; u < 6; u++) {
                int cc = col0 - 1 + u;
                float val = 0.f;
                if ((unsigned)cc < 64u)
                    val = (ic == 64) ? ((float)cc * (2.f / 63.f) - 1.f) : yyv;
                v[u] = val;
            }
            const float* wr = &ws[ic * 9 + kh * 3];
            #pragma unroll
            for (int kw = 0; kw < 3; kw++) {
                float wv = wr[kw];
                acc[0] += wv * v[kw + 0];
                acc[1] += wv * v[kw + 1];
                acc[2] += wv * v[kw + 2];
                acc[3] += wv * v[kw + 3];
            }
        }
    }

    float s = g_scale[z * CH + oc];
    float* op = out + oc * HW + p;
    op[0] = s * acc[0];
    op[1] = s * acc[1];
    op[2] = s * acc[2];
    op[3] = s * acc[3];
}

// ---------------- 3. fused QKV projections (f32x2) ----------------
// grid (32, 8, 4), block 128. z: 0,1 -> x-side (q,k,v) for batch z; 2,3 -> g-side (q,k).
__global__ void __launch_bounds__(128) kproj(
    const float* __restrict__ xq_w, const float* __restrict__ xq_b,
    const float* __restrict__ xk_w, const float* __restrict__ xk_b,
    const float* __restrict__ xv_w, const float* __restrict__ xv_b,
    const float* __restrict__ gq_w, const float* __restrict__ gq_b,
    const float* __restrict__ gk_w, const float* __restrict__ gk_b) {
    __shared__ float si[64 * 128];
    __shared__ float swt[3 * 512];   // transposed weights [set][c*8+o]
    __shared__ float sb[3 * 8];

    int z = blockIdx.z;
    int side = z >> 1, b = z & 1;
    int og = blockIdx.y;
    int n0 = blockIdx.x * 128;
    int tid = threadIdx.x;

    const float* in = (side ? g_gg : g_xg) + b * CH * HW;
    const float* ws[3];
    const float* bs[3];
    float* outs[3];
    int nset;
    if (side == 0) {
        ws[0] = xq_w; ws[1] = xk_w; ws[2] = xv_w;
        bs[0] = xq_b; bs[1] = xk_b; bs[2] = xv_b;
        outs[0] = g_xq; outs[1] = g_xk; outs[2] = g_xv;
        nset = 3;
    } else {
        ws[0] = gq_w; ws[1] = gk_w; ws[2] = gk_w;
        bs[0] = gq_b; bs[1] = gk_b; bs[2] = gk_b;
        outs[0] = g_gq; outs[1] = g_gk; outs[2] = g_gk;
        nset = 2;
    }

    // stage input tile (vectorized)
    #pragma unroll
    for (int u = 0; u < 16; u++) {
        int idx4 = tid + u * 128;            // 0..2047 float4 units
        int c = idx4 >> 4, p4 = (idx4 & 15) * 8;  // 16 float4 = 128 px per c? -> fix: 32 per c
        (void)c; (void)p4;
    }
    for (int i = tid; i < 2048; i += 128) {   // 2048 float4 units = 8192 floats
        int c = i >> 5, p4 = (i & 31) * 4;
        *(float4*)(si + c * 128 + p4) = *(const float4*)(in + c * HW + n0 + p4);
    }
    // stage weights transposed
    for (int s = 0; s < nset; s++) {
        for (int i = tid; i < 512; i += 128) {
            int c = i >> 3, o = i & 7;
            swt[s * 512 + c * 8 + o] = ws[s][(og * 8 + o) * 64 + c];
        }
        if (tid < 8) sb[s * 8 + tid] = bs[s][og * 8 + tid];
    }
    __syncthreads();

    u64 acc[3][4];
    #pragma unroll
    for (int s = 0; s < 3; s++)
        #pragma unroll
        for (int k = 0; k < 4; k++)
            acc[s][k] = pk2(sb[s * 8 + 2 * k], sb[s * 8 + 2 * k + 1]);

    if (side == 0) {
        for (int c = 0; c < 64; c++) {
            float iv = si[c * 128 + tid];
            u64 ivp = pk2(iv, iv);
            #pragma unroll
            for (int s = 0; s < 3; s++) {
                ulonglong2 wa = *(const ulonglong2*)(swt + s * 512 + c * 8);
                ulonglong2 wb = *(const ulonglong2*)(swt + s * 512 + c * 8 + 4);
                acc[s][0] = ffma2(ivp, wa.x, acc[s][0]);
                acc[s][1] = ffma2(ivp, wa.y, acc[s][1]);
                acc[s][2] = ffma2(ivp, wb.x, acc[s][2]);
                acc[s][3] = ffma2(ivp, wb.y, acc[s][3]);
            }
        }
    } else {
        for (int c = 0; c < 64; c++) {
            float iv = si[c * 128 + tid];
            u64 ivp = pk2(iv, iv);
            #pragma unroll
            for (int s = 0; s < 2; s++) {
                ulonglong2 wa = *(const ulonglong2*)(swt + s * 512 + c * 8);
                ulonglong2 wb = *(const ulonglong2*)(swt + s * 512 + c * 8 + 4);
                acc[s][0] = ffma2(ivp, wa.x, acc[s][0]);
                acc[s][1] = ffma2(ivp, wa.y, acc[s][1]);
                acc[s][2] = ffma2(ivp, wb.x, acc[s][2]);
                acc[s][3] = ffma2(ivp, wb.y, acc[s][3]);
            }
        }
    }

    for (int s = 0; s < nset; s++) {
        #pragma unroll
        for (int k = 0; k < 4; k++) {
            float lo, hi;
            upk2(acc[s][k], lo, hi);
            outs[s][(b * CH + og * 8 + 2 * k) * HW + n0 + tid] = lo;
            outs[s][(b * CH + og * 8 + 2 * k + 1) * HW + n0 + tid] = hi;
        }
    }
}

// ---------------- 4. flash attention (f32x2) ----------------
// grid (64, B, 2), block 256 = 16x16, 4x4 micro, smem 66816 B
__global__ void __launch_bounds__(256, 2) kflash() {
    extern __shared__ float sm[];
    float* Qs = sm;                 // [64][64]  Qs[c*64+n]
    float* Ks = Qs + 4096;          // [64][64]  Ks[c*64+m]
    float* Vs = Ks + 4096;          // [64][65]  Vs[c*65+m]  (pad 65: conflict-free col reads)
    float* Pt = Vs + 64 * 65;       // [64][68]  transposed P: Pt[j][i], swizzled slots

    int b = blockIdx.y, kind = blockIdx.z;
    int n0 = blockIdx.x * 64;
    const float* Q = (kind ? g_gq : g_xq) + b * CH * HW;
    const float* K = (kind ? g_gk : g_xk) + b * CH * HW;
    const float* V = g_xv + b * CH * HW;
    float* O = (kind ? g_gout : g_xout) + b * CH * HW;

    int tid = threadIdx.x;
    int tx = tid & 15, ty = tid >> 4;   // rows 4*ty+ii, cols 4*tx+jj

    // stage Q once (vectorized)
    #pragma unroll
    for (int u = 0; u < 4; u++) {
        int i4 = tid + u * 256;              // 1024 float4 units
        int c = i4 >> 4, m4 = (i4 & 15) * 4;
        *(float4*)(Qs + c * 64 + m4) = *(const float4*)(Q + c * HW + n0 + m4);
    }

    u64 o2[2][4];        // rows pairs (ii0,ii1),(ii2,ii3) x channels s2
    float m[4], l[4];
    #pragma unroll
    for (int r = 0; r < 2; r++)
        #pragma unroll
        for (int s2 = 0; s2 < 4; s2++) o2[r][s2] = 0ULL;
    #pragma unroll
    for (int ii = 0; ii < 4; ii++) { m[ii] = -1e30f; l[ii] = 0.f; }

    for (int kt = 0; kt < 64; kt++) {
        int m0 = kt * 64;
        __syncthreads();
        // stage K (vectorized) and V (vector load, scalar store to padded)
        #pragma unroll
        for (int u = 0; u < 4; u++) {
            int i4 = tid + u * 256;
            int c = i4 >> 4, m4 = (i4 & 15) * 4;
            *(float4*)(Ks + c * 64 + m4) = *(const float4*)(K + c * HW + m0 + m4);
            float4 gv = *(const float4*)(V + c * HW + m0 + m4);
            float* vp = Vs + c * 65 + m4;
            vp[0] = gv.x; vp[1] = gv.y; vp[2] = gv.z; vp[3] = gv.w;
        }
        __syncthreads();

        // ---- QK^T: s[i][j] = sum_c Q[c][i] K[c][j] ----
        u64 s2[2][4];
        #pragma unroll
        for (int r = 0; r < 2; r++)
            #pragma unroll
            for (int jj = 0; jj < 4; jj++) s2[r][jj] = 0ULL;

        #pragma unroll 8
        for (int c = 0; c < 64; c++) {
            ulonglong2 qp = *(const ulonglong2*)(Qs + c * 64 + 4 * ty);
            float4 kf = *(const float4*)(Ks + c * 64 + 4 * tx);
            u64 k0 = pk2(kf.x, kf.x), k1 = pk2(kf.y, kf.y);
            u64 k2 = pk2(kf.z, kf.z), k3 = pk2(kf.w, kf.w);
            s2[0][0] = ffma2(qp.x, k0, s2[0][0]);
            s2[0][1] = ffma2(qp.x, k1, s2[0][1]);
            s2[0][2] = ffma2(qp.x, k2, s2[0][2]);
            s2[0][3] = ffma2(qp.x, k3, s2[0][3]);
            s2[1][0] = ffma2(qp.y, k0, s2[1][0]);
            s2[1][1] = ffma2(qp.y, k1, s2[1][1]);
            s2[1][2] = ffma2(qp.y, k2, s2[1][2]);
            s2[1][3] = ffma2(qp.y, k3, s2[1][3]);
        }

        float s[4][4];
        #pragma unroll
        for (int jj = 0; jj < 4; jj++) {
            upk2(s2[0][jj], s[0][jj], s[1][jj]);
            upk2(s2[1][jj], s[2][jj], s[3][jj]);
        }

        // ---- online softmax (row groups across 16 tx lanes) ----
        float p[4][4], corr[4];
        #pragma unroll
        for (int ii = 0; ii < 4; ii++) {
            float tm = fmaxf(fmaxf(s[ii][0], s[ii][1]), fmaxf(s[ii][2], s[ii][3]));
            #pragma unroll
            for (int off = 1; off < 16; off <<= 1)
                tm = fmaxf(tm, __shfl_xor_sync(0xffffffffu, tm, off));
            float mn = fmaxf(m[ii], tm);
            float ps = 0.f;
            #pragma unroll
            for (int jj = 0; jj < 4; jj++) { p[ii][jj] = __expf(s[ii][jj] - mn); ps += p[ii][jj]; }
            #pragma unroll
            for (int off = 1; off < 16; off <<= 1)
                ps += __shfl_xor_sync(0xffffffffu, ps, off);
            corr[ii] = __expf(m[ii] - mn);
            l[ii] = l[ii] * corr[ii] + ps;
            m[ii] = mn;
        }
        u64 cp0 = pk2(corr[0], corr[1]);
        u64 cp1 = pk2(corr[2], corr[3]);
        #pragma unroll
        for (int s2i = 0; s2i < 4; s2i++) {
            o2[0][s2i] = fmul2(o2[0][s2i], cp0);
            o2[1][s2i] = fmul2(o2[1][s2i], cp1);
        }
        // store P transposed: Pt[j][rows 4ty..4ty+3], swizzled float4 slot
        #pragma unroll
        for (int jj = 0; jj < 4; jj++) {
            int j = 4 * tx + jj;
            int slot = ty ^ ((j >> 1) & 15);
            *(float4*)(Pt + j * 68 + 4 * slot) =
                make_float4(p[0][jj], p[1][jj], p[2][jj], p[3][jj]);
        }
        __syncthreads();

        // ---- PV: O[c][i] += sum_j P[i][j] V[c][j] ----
        #pragma unroll 4
        for (int j = 0; j < 64; j++) {
            int slot = ty ^ ((j >> 1) & 15);
            ulonglong2 pp = *(const ulonglong2*)(Pt + j * 68 + 4 * slot);
            float v0 = Vs[(4 * tx + 0) * 65 + j];
            float v1 = Vs[(4 * tx + 1) * 65 + j];
            float v2 = Vs[(4 * tx + 2) * 65 + j];
            float v3 = Vs[(4 * tx + 3) * 65 + j];
            u64 vb0 = pk2(v0, v0), vb1 = pk2(v1, v1);
            u64 vb2 = pk2(v2, v2), vb3 = pk2(v3, v3);
            o2[0][0] = ffma2(pp.x, vb0, o2[0][0]);
            o2[0][1] = ffma2(pp.x, vb1, o2[0][1]);
            o2[0][2] = ffma2(pp.x, vb2, o2[0][2]);
            o2[0][3] = ffma2(pp.x, vb3, o2[0][3]);
            o2[1][0] = ffma2(pp.y, vb0, o2[1][0]);
            o2[1][1] = ffma2(pp.y, vb1, o2[1][1]);
            o2[1][2] = ffma2(pp.y, vb2, o2[1][2]);
            o2[1][3] = ffma2(pp.y, vb3, o2[1][3]);
        }
    }

    // epilogue: divide by l, write out (float4 per channel over 4 rows)
    float oo[4][4];   // [ii][s2]
    #pragma unroll
    for (int s2i = 0; s2i < 4; s2i++) {
        upk2(o2[0][s2i], oo[0][s2i], oo[1][s2i]);
        upk2(o2[1][s2i], oo[2][s2i], oo[3][s2i]);
    }
    float inv[4];
    #pragma unroll
    for (int ii = 0; ii < 4; ii++) inv[ii] = 1.f / l[ii];
    #pragma unroll
    for (int s2i = 0; s2i < 4; s2i++) {
        int c = 4 * tx + s2i;
        float4 w4 = make_float4(oo[0][s2i] * inv[0], oo[1][s2i] * inv[1],
                                oo[2][s2i] * inv[2], oo[3][s2i] * inv[3]);
        *(float4*)(O + c * HW + n0 + 4 * ty) = w4;
    }
}

// ---------------- 5. combine ----------------
__global__ void kcombine(const float* __restrict__ gamma, const float* __restrict__ alpha) {
    int i = blockIdx.x * 256 + threadIdx.x;
    g_outb[i] = gamma[0] * g_xout[i] + alpha[0] * g_gout[i];
}

// ---------------- 6. plain conv3x3 ----------------
__global__ void kconv3(const float* __restrict__ w, const float* __restrict__ bias,
                       int in_id, int out_id, int leaky_in) {
    const float* inb = pick_in(in_id);
    float* outb = pick_out(out_id);
    int b = blockIdx.z, oc = blockIdx.y;

    __shared__ float ws[576];
    for (int i = threadIdx.x; i < 576; i += 256) ws[i] = w[oc * 576 + i];
    __syncthreads();

    int p = blockIdx.x * 1024 + threadIdx.x * 4;
    int row = p >> 6, col0 = p & 63;
    float bv = bias[oc];
    float acc[4] = {bv, bv, bv, bv};
    const float* in = inb + b * CH * HW;

    for (int ic = 0; ic < 64; ic++) {
        const float* ch = in + ic * HW;
        #pragma unroll
        for (int kh = 0; kh < 3; kh++) {
            int hh = row + kh - 1;
            if ((unsigned)hh >= 64u) continue;
            float v[6];
            #pragma unroll
            for (int u = 0; u < 6; u++) {
                int cc = col0 - 1 + u;
                float val = ((unsigned)cc < 64u) ? ch[hh * 64 + cc] : 0.f;
                if (leaky_in) val = val > 0.f ? val : 0.1f * val;
                v[u] = val;
            }
            const float* wr = &ws[ic * 9 + kh * 3];
            #pragma unroll
            for (int kw = 0; kw < 3; kw++) {
                float wv = wr[kw];
                acc[0] += wv * v[kw + 0];
                acc[1] += wv * v[kw + 1];
                acc[2] += wv * v[kw + 2];
                acc[3] += wv * v[kw + 3];
            }
        }
    }
    float* op = outb + (b * CH + oc) * HW + p;
    op[0] = acc[0]; op[1] = acc[1]; op[2] = acc[2]; op[3] = acc[3];
}

// ---------------- 3b. 1x1 conv (shortcut path) ----------------
__global__ void k1x1(const float* __restrict__ w, const float* __restrict__ bias,
                     int in_id, int out_id) {
    const float* in = pick_in(in_id);
    float* out = pick_out(out_id);
    int b = blockIdx.z, og = blockIdx.y;
    int n0 = blockIdx.x * 128;

    __shared__ float si[64 * 128];
    __shared__ float sw[8 * 64];
    for (int i = threadIdx.x; i < 64 * 128; i += 128) {
        int c = i >> 7, px = i & 127;
        si[i] = in[(b * CH + c) * HW + n0 + px];
    }
    for (int i = threadIdx.x; i < 512; i += 128)
        sw[i] = w[(og * 8 + (i >> 6)) * 64 + (i & 63)];
    __syncthreads();

    float acc[8];
    #pragma unroll
    for (int o = 0; o < 8; o++) acc[o] = bias[og * 8 + o];
    for (int c = 0; c < 64; c++) {
        float iv = si[c * 128 + threadIdx.x];
        #pragma unroll
        for (int o = 0; o < 8; o++) acc[o] += sw[o * 64 + c] * iv;
    }
    #pragma unroll
    for (int o = 0; o < 8; o++)
        out[(b * CH + og * 8 + o) * HW + n0 + threadIdx.x] = acc[o];
}

// ---------------- 7. final ----------------
__global__ void kfinal(float* __restrict__ dout) {
    int i = blockIdx.x * 256 + threadIdx.x;
    dout[i] = g_t2[i] + g_sc[i] * g_gout[i];
}

extern "C" void kernel_launch(void* const* d_in, const int* in_sizes, int n_in,
                              void* d_out, int out_size) {
    const float* x       = (const float*)d_in[0];
    const float* guide   = (const float*)d_in[1];
    const float* lin_w   = (const float*)d_in[2];
    const float* lin_b   = (const float*)d_in[3];
    const float* coord_w = (const float*)d_in[4];
    const float* xq_w = (const float*)d_in[5];
    const float* xq_b = (const float*)d_in[6];
    const float* xk_w = (const float*)d_in[7];
    const float* xk_b = (const float*)d_in[8];
    const float* xv_w = (const float*)d_in[9];
    const float* xv_b = (const float*)d_in[10];
    const float* gq_w = (const float*)d_in[11];
    const float* gq_b = (const float*)d_in[12];
    const float* gk_w = (const float*)d_in[13];
    const float* gk_b = (const float*)d_in[14];
    const float* gamma = (const float*)d_in[15];
    const float* alpha = (const float*)d_in[16];
    const float* c1_w = (const float*)d_in[17];
    const float* c1_b = (const float*)d_in[18];
    const float* c2_w = (const float*)d_in[19];
    const float* c2_b = (const float*)d_in[20];
    const float* sc_w = (const float*)d_in[21];
    const float* sc_b = (const float*)d_in[22];
    float* out = (float*)d_out;

    cudaFuncSetAttribute(kflash, cudaFuncAttributeMaxDynamicSharedMemorySize, 66816);

    kstats<<<256, 256>>>(x, guide, lin_w, lin_b);
    kgated<<<dim3(4, 64, 4), 256>>>(x, guide, coord_w);

    kproj<<<dim3(32, 8, 4), 128>>>(xq_w, xq_b, xk_w, xk_b, xv_w, xv_b,
                                   gq_w, gq_b, gk_w, gk_b);

    kflash<<<dim3(64, BATCH, 2), 256, 66816>>>();

    kcombine<<<2048, 256>>>(gamma, alpha);

    kconv3<<<dim3(4, 64, BATCH), 256>>>(c1_w, c1_b, BUF_OUT, BUF_OT1, 1);
    kconv3<<<dim3(4, 64, BATCH), 256>>>(c2_w, c2_b, BUF_T1, BUF_OT2, 1);

    k1x1<<<dim3(32, 8, BATCH), 128>>>(sc_w, sc_b, BUF_OUT, BUF_SC);

    kfinal<<<2048, 256>>>(out);
}

// round 3
// speedup vs baseline: 1.4923x; 1.2732x over previous
#include <cuda_runtime.h>
#include <cuda_bf16.h>

#define BATCH 2
#define CH 64
#define HW 4096   // 64*64

typedef unsigned long long u64;

__device__ __forceinline__ u64 pk2(float lo, float hi) {
    u64 r; asm("mov.b64 %0,{%1,%2};" : "=l"(r) : "f"(lo), "f"(hi)); return r;
}
__device__ __forceinline__ void upk2(u64 v, float& lo, float& hi) {
    asm("mov.b64 {%0,%1},%2;" : "=f"(lo), "=f"(hi) : "l"(v));
}
__device__ __forceinline__ u64 ffma2(u64 a, u64 b, u64 c) {
    u64 d; asm("fma.rn.f32x2 %0,%1,%2,%3;" : "=l"(d) : "l"(a), "l"(b), "l"(c)); return d;
}
__device__ __forceinline__ u64 fmul2(u64 a, u64 b) {
    u64 d; asm("mul.rn.f32x2 %0,%1,%2;" : "=l"(d) : "l"(a), "l"(b)); return d;
}

// ---------------- scratch ----------------
__device__ float g_scale[4 * CH];
__device__ float g_xg[BATCH * CH * HW];
__device__ float g_gg[BATCH * CH * HW];
__device__ float g_xq[BATCH * CH * HW];
__device__ float g_xk[BATCH * CH * HW];
__device__ float g_xv[BATCH * CH * HW];
__device__ float g_gq[BATCH * CH * HW];
__device__ float g_gk[BATCH * CH * HW];
__device__ float g_xout[BATCH * CH * HW];
__device__ float g_gout[BATCH * CH * HW];
__device__ float g_outb[BATCH * CH * HW];
__device__ float g_t1[BATCH * CH * HW];
__device__ float g_t2[BATCH * CH * HW];
__device__ float g_sc[BATCH * CH * HW];

#define BUF_XG 0
#define BUF_GG 1
#define BUF_OUT 2
#define BUF_T1 3

#define BUF_XQ 0
#define BUF_XK 1
#define BUF_XV 2
#define BUF_GQ 3
#define BUF_GK 4
#define BUF_SC 5
#define BUF_OT1 6
#define BUF_OT2 7

__device__ __forceinline__ float* pick_in(int w) {
    switch (w) {
        case BUF_XG: return g_xg;
        case BUF_GG: return g_gg;
        case BUF_OUT: return g_outb;
        default:     return g_t1;
    }
}
__device__ __forceinline__ float* pick_out(int w) {
    switch (w) {
        case BUF_XQ: return g_xq;
        case BUF_XK: return g_xk;
        case BUF_XV: return g_xv;
        case BUF_GQ: return g_gq;
        case BUF_GK: return g_gk;
        case BUF_SC: return g_sc;
        case BUF_OT1: return g_t1;
        default:      return g_t2;
    }
}

// ---------------- 1. channel attention scalars ----------------
__global__ void kstats(const float* __restrict__ x, const float* __restrict__ g,
                       const float* __restrict__ lw, const float* __restrict__ lb) {
    int idx = blockIdx.x;
    int t = idx >> 7, b = (idx >> 6) & 1, c = idx & 63;
    const float* in = (t ? g : x) + (b * CH + c) * HW;
    float s = 0.f;
    for (int i = threadIdx.x; i < HW; i += 256) s += in[i];
    __shared__ float red[8];
    #pragma unroll
    for (int o = 16; o > 0; o >>= 1) s += __shfl_xor_sync(0xffffffffu, s, o);
    if ((threadIdx.x & 31) == 0) red[threadIdx.x >> 5] = s;
    __syncthreads();
    if (threadIdx.x == 0) {
        float tot = 0.f;
        #pragma unroll
        for (int i = 0; i < 8; i++) tot += red[i];
        float p = tot * (1.0f / (float)HW);
        float W = lw[0], B = lb[0];
        float h = p * W + B;
        h = h > 0.f ? h : 0.1f * h;
        float z = h * W + B;
        g_scale[idx] = 1.f / (1.f + expf(-z));
    }
}

// ---------------- 2. gated coord conv: 4 oc per block ----------------
// grid (4, 16, 4), block 256
__global__ void __launch_bounds__(256) kgated(const float* __restrict__ xin,
                                              const float* __restrict__ gin,
                                              const float* __restrict__ cw) {
    int z = blockIdx.z;
    int t = z >> 1, b = z & 1;
    const float* in = (t ? gin : xin) + b * CH * HW;
    float* out = (t ? g_gg : g_xg) + b * CH * HW;
    int ocg = blockIdx.y;   // 16 groups of 4 oc

    __shared__ float ws[4 * 66 * 9];
    for (int i = threadIdx.x; i < 4 * 66 * 9; i += 256) {
        int o = i / 594, r = i % 594;
        ws[o * 594 + r] = cw[(ocg * 4 + o) * 594 + r];
    }
    __syncthreads();

    int p = blockIdx.x * 1024 + threadIdx.x * 4;
    int row = p >> 6, col0 = p & 63;
    float acc[4][4];
    #pragma unroll
    for (int o = 0; o < 4; o++)
        #pragma unroll
        for (int u = 0; u < 4; u++) acc[o][u] = 0.f;

    for (int ic = 0; ic < 64; ic++) {
        const float* ch = in + ic * HW;
        #pragma unroll
        for (int kh = 0; kh < 3; kh++) {
            int hh = row + kh - 1;
            if ((unsigned)hh >= 64u) continue;
            float v[6];
            #pragma unroll
            for (int u = 0; u < 6; u++) {
                int cc = col0 - 1 + u;
                v[u] = ((unsigned)cc < 64u) ? ch[hh * 64 + cc] : 0.f;
            }
            #pragma unroll
            for (int o = 0; o < 4; o++) {
                const float* wr = &ws[o * 594 + ic * 9 + kh * 3];
                #pragma unroll
                for (int kw = 0; kw < 3; kw++) {
                    float wv = wr[kw];
                    acc[o][0] += wv * v[kw + 0];
                    acc[o][1] += wv * v[kw + 1];
                    acc[o][2] += wv * v[kw + 2];
                    acc[o][3] += wv * v[kw + 3];
                }
            }
        }
    }
    // coord channels ic=64 (xx, varies with col), ic=65 (yy, varies with row)
    #pragma unroll
    for (int ic = 64; ic < 66; ic++) {
        #pragma unroll
        for (int kh = 0; kh < 3; kh++) {
            int hh = row + kh - 1;
            if ((unsigned)hh >= 64u) continue;
            float yyv = (float)hh * (2.f / 63.f) - 1.f;
            float v[6];
            #pragma unroll
            for (int u = 0; u < 6; u++) {
                int cc = col0 - 1 + u;
                float val = 0.f;
                if ((unsigned)cc < 64u)
                    val = (ic == 64) ? ((float)cc * (2.f / 63.f) - 1.f) : yyv;
                v[u] = val;
            }
            #pragma unroll
            for (int o = 0; o < 4; o++) {
                const float* wr = &ws[o * 594 + ic * 9 + kh * 3];
                #pragma unroll
                for (int kw = 0; kw < 3; kw++) {
                    float wv = wr[kw];
                    acc[o][0] += wv * v[kw + 0];
                    acc[o][1] += wv * v[kw + 1];
                    acc[o][2] += wv * v[kw + 2];
                    acc[o][3] += wv * v[kw + 3];
                }
            }
        }
    }

    #pragma unroll
    for (int o = 0; o < 4; o++) {
        int oc = ocg * 4 + o;
        float s = g_scale[z * CH + oc];
        float* op = out + oc * HW + p;
        float4 w4 = make_float4(s * acc[o][0], s * acc[o][1], s * acc[o][2], s * acc[o][3]);
        *(float4*)op = w4;
    }
}

// ---------------- 3. fused QKV projections (f32x2) ----------------
__global__ void __launch_bounds__(128) kproj(
    const float* __restrict__ xq_w, const float* __restrict__ xq_b,
    const float* __restrict__ xk_w, const float* __restrict__ xk_b,
    const float* __restrict__ xv_w, const float* __restrict__ xv_b,
    const float* __restrict__ gq_w, const float* __restrict__ gq_b,
    const float* __restrict__ gk_w, const float* __restrict__ gk_b) {
    __shared__ float si[64 * 128];
    __shared__ float swt[3 * 512];
    __shared__ float sb[3 * 8];

    int z = blockIdx.z;
    int side = z >> 1, b = z & 1;
    int og = blockIdx.y;
    int n0 = blockIdx.x * 128;
    int tid = threadIdx.x;

    const float* in = (side ? g_gg : g_xg) + b * CH * HW;
    const float* ws[3];
    const float* bs[3];
    float* outs[3];
    int nset;
    if (side == 0) {
        ws[0] = xq_w; ws[1] = xk_w; ws[2] = xv_w;
        bs[0] = xq_b; bs[1] = xk_b; bs[2] = xv_b;
        outs[0] = g_xq; outs[1] = g_xk; outs[2] = g_xv;
        nset = 3;
    } else {
        ws[0] = gq_w; ws[1] = gk_w; ws[2] = gk_w;
        bs[0] = gq_b; bs[1] = gk_b; bs[2] = gk_b;
        outs[0] = g_gq; outs[1] = g_gk; outs[2] = g_gk;
        nset = 2;
    }

    for (int i = tid; i < 2048; i += 128) {
        int c = i >> 5, p4 = (i & 31) * 4;
        *(float4*)(si + c * 128 + p4) = *(const float4*)(in + c * HW + n0 + p4);
    }
    for (int s = 0; s < nset; s++) {
        for (int i = tid; i < 512; i += 128) {
            int c = i >> 3, o = i & 7;
            swt[s * 512 + c * 8 + o] = ws[s][(og * 8 + o) * 64 + c];
        }
        if (tid < 8) sb[s * 8 + tid] = bs[s][og * 8 + tid];
    }
    __syncthreads();

    u64 acc[3][4];
    #pragma unroll
    for (int s = 0; s < 3; s++)
        #pragma unroll
        for (int k = 0; k < 4; k++)
            acc[s][k] = pk2(sb[s * 8 + 2 * k], sb[s * 8 + 2 * k + 1]);

    if (side == 0) {
        for (int c = 0; c < 64; c++) {
            float iv = si[c * 128 + tid];
            u64 ivp = pk2(iv, iv);
            #pragma unroll
            for (int s = 0; s < 3; s++) {
                ulonglong2 wa = *(const ulonglong2*)(swt + s * 512 + c * 8);
                ulonglong2 wb = *(const ulonglong2*)(swt + s * 512 + c * 8 + 4);
                acc[s][0] = ffma2(ivp, wa.x, acc[s][0]);
                acc[s][1] = ffma2(ivp, wa.y, acc[s][1]);
                acc[s][2] = ffma2(ivp, wb.x, acc[s][2]);
                acc[s][3] = ffma2(ivp, wb.y, acc[s][3]);
            }
        }
    } else {
        for (int c = 0; c < 64; c++) {
            float iv = si[c * 128 + tid];
            u64 ivp = pk2(iv, iv);
            #pragma unroll
            for (int s = 0; s < 2; s++) {
                ulonglong2 wa = *(const ulonglong2*)(swt + s * 512 + c * 8);
                ulonglong2 wb = *(const ulonglong2*)(swt + s * 512 + c * 8 + 4);
                acc[s][0] = ffma2(ivp, wa.x, acc[s][0]);
                acc[s][1] = ffma2(ivp, wa.y, acc[s][1]);
                acc[s][2] = ffma2(ivp, wb.x, acc[s][2]);
                acc[s][3] = ffma2(ivp, wb.y, acc[s][3]);
            }
        }
    }

    for (int s = 0; s < nset; s++) {
        #pragma unroll
        for (int k = 0; k < 4; k++) {
            float lo, hi;
            upk2(acc[s][k], lo, hi);
            outs[s][(b * CH + og * 8 + 2 * k) * HW + n0 + tid] = lo;
            outs[s][(b * CH + og * 8 + 2 * k + 1) * HW + n0 + tid] = hi;
        }
    }
}

// ---------------- 4. flash attention (f32x2, swizzled V) ----------------
// grid (64, B, 2), block 256 = 16x16, 4x4 micro
// smem: Qs[64*64] Ks[64*64] Vs[64*64 swizzled float4 chunks] Pt[64*68]
__global__ void __launch_bounds__(256, 2) kflash() {
    extern __shared__ float sm[];
    float* Qs = sm;                 // Qs[c*64 + n]
    float* Ks = Qs + 4096;          // Ks[c*64 + m]
    float* Vs = Ks + 4096;          // Vs[c*64 + 4*(jc ^ ((c>>2)&15))] : V[c][4jc..4jc+3]
    float* Pt = Vs + 4096;          // Pt[j*68 + 4*slot] float4 = rows 4ty..4ty+3 at col j

    int b = blockIdx.y, kind = blockIdx.z;
    int n0 = blockIdx.x * 64;
    const float* Q = (kind ? g_gq : g_xq) + b * CH * HW;
    const float* K = (kind ? g_gk : g_xk) + b * CH * HW;
    const float* V = g_xv + b * CH * HW;
    float* O = (kind ? g_gout : g_xout) + b * CH * HW;

    int tid = threadIdx.x;
    int tx = tid & 15, ty = tid >> 4;

    #pragma unroll
    for (int u = 0; u < 4; u++) {
        int i4 = tid + u * 256;
        int c = i4 >> 4, m4 = (i4 & 15) * 4;
        *(float4*)(Qs + c * 64 + m4) = *(const float4*)(Q + c * HW + n0 + m4);
    }

    u64 o2[2][4];
    float m[4], l[4];
    #pragma unroll
    for (int r = 0; r < 2; r++)
        #pragma unroll
        for (int s2 = 0; s2 < 4; s2++) o2[r][s2] = 0ULL;
    #pragma unroll
    for (int ii = 0; ii < 4; ii++) { m[ii] = -1e30f; l[ii] = 0.f; }

    for (int kt = 0; kt < 64; kt++) {
        int m0 = kt * 64;
        __syncthreads();
        #pragma unroll
        for (int u = 0; u < 4; u++) {
            int i4 = tid + u * 256;
            int c = i4 >> 4, jc_s = i4 & 15;
            *(float4*)(Ks + c * 64 + jc_s * 4) = *(const float4*)(K + c * HW + m0 + jc_s * 4);
            float4 gv = *(const float4*)(V + c * HW + m0 + jc_s * 4);
            *(float4*)(Vs + c * 64 + 4 * (jc_s ^ ((c >> 2) & 15))) = gv;
        }
        __syncthreads();

        // ---- QK^T ----
        u64 s2[2][4];
        #pragma unroll
        for (int r = 0; r < 2; r++)
            #pragma unroll
            for (int jj = 0; jj < 4; jj++) s2[r][jj] = 0ULL;

        #pragma unroll 8
        for (int c = 0; c < 64; c++) {
            ulonglong2 qp = *(const ulonglong2*)(Qs + c * 64 + 4 * ty);
            float4 kf = *(const float4*)(Ks + c * 64 + 4 * tx);
            u64 k0 = pk2(kf.x, kf.x), k1 = pk2(kf.y, kf.y);
            u64 k2 = pk2(kf.z, kf.z), k3 = pk2(kf.w, kf.w);
            s2[0][0] = ffma2(qp.x, k0, s2[0][0]);
            s2[0][1] = ffma2(qp.x, k1, s2[0][1]);
            s2[0][2] = ffma2(qp.x, k2, s2[0][2]);
            s2[0][3] = ffma2(qp.x, k3, s2[0][3]);
            s2[1][0] = ffma2(qp.y, k0, s2[1][0]);
            s2[1][1] = ffma2(qp.y, k1, s2[1][1]);
            s2[1][2] = ffma2(qp.y, k2, s2[1][2]);
            s2[1][3] = ffma2(qp.y, k3, s2[1][3]);
        }

        float s[4][4];
        #pragma unroll
        for (int jj = 0; jj < 4; jj++) {
            upk2(s2[0][jj], s[0][jj], s[1][jj]);
            upk2(s2[1][jj], s[2][jj], s[3][jj]);
        }

        // ---- online softmax ----
        float p[4][4], corr[4];
        #pragma unroll
        for (int ii = 0; ii < 4; ii++) {
            float tm = fmaxf(fmaxf(s[ii][0], s[ii][1]), fmaxf(s[ii][2], s[ii][3]));
            #pragma unroll
            for (int off = 1; off < 16; off <<= 1)
                tm = fmaxf(tm, __shfl_xor_sync(0xffffffffu, tm, off));
            float mn = fmaxf(m[ii], tm);
            float ps = 0.f;
            #pragma unroll
            for (int jj = 0; jj < 4; jj++) { p[ii][jj] = __expf(s[ii][jj] - mn); ps += p[ii][jj]; }
            #pragma unroll
            for (int off = 1; off < 16; off <<= 1)
                ps += __shfl_xor_sync(0xffffffffu, ps, off);
            corr[ii] = __expf(m[ii] - mn);
            l[ii] = l[ii] * corr[ii] + ps;
            m[ii] = mn;
        }
        u64 cp0 = pk2(corr[0], corr[1]);
        u64 cp1 = pk2(corr[2], corr[3]);
        #pragma unroll
        for (int s2i = 0; s2i < 4; s2i++) {
            o2[0][s2i] = fmul2(o2[0][s2i], cp0);
            o2[1][s2i] = fmul2(o2[1][s2i], cp1);
        }
        #pragma unroll
        for (int jj = 0; jj < 4; jj++) {
            int j = 4 * tx + jj;
            int slot = ty ^ ((j >> 1) & 15);
            *(float4*)(Pt + j * 68 + 4 * slot) =
                make_float4(p[0][jj], p[1][jj], p[2][jj], p[3][jj]);
        }
        __syncthreads();

        // ---- PV: chunked j, vectorized conflict-free V reads ----
        #pragma unroll 2
        for (int jc = 0; jc < 16; jc++) {
            float va[4][4];
            #pragma unroll
            for (int s2i = 0; s2i < 4; s2i++) {
                float4 v4 = *(const float4*)(Vs + (4 * tx + s2i) * 64 + 4 * (jc ^ tx));
                va[s2i][0] = v4.x; va[s2i][1] = v4.y; va[s2i][2] = v4.z; va[s2i][3] = v4.w;
            }
            #pragma unroll
            for (int jj = 0; jj < 4; jj++) {
                int j = 4 * jc + jj;
                int slot = ty ^ ((j >> 1) & 15);
                ulonglong2 pp = *(const ulonglong2*)(Pt + j * 68 + 4 * slot);
                u64 vb0 = pk2(va[0][jj], va[0][jj]);
                u64 vb1 = pk2(va[1][jj], va[1][jj]);
                u64 vb2 = pk2(va[2][jj], va[2][jj]);
                u64 vb3 = pk2(va[3][jj], va[3][jj]);
                o2[0][0] = ffma2(pp.x, vb0, o2[0][0]);
                o2[0][1] = ffma2(pp.x, vb1, o2[0][1]);
                o2[0][2] = ffma2(pp.x, vb2, o2[0][2]);
                o2[0][3] = ffma2(pp.x, vb3, o2[0][3]);
                o2[1][0] = ffma2(pp.y, vb0, o2[1][0]);
                o2[1][1] = ffma2(pp.y, vb1, o2[1][1]);
                o2[1][2] = ffma2(pp.y, vb2, o2[1][2]);
                o2[1][3] = ffma2(pp.y, vb3, o2[1][3]);
            }
        }
    }

    float oo[4][4];
    #pragma unroll
    for (int s2i = 0; s2i < 4; s2i++) {
        upk2(o2[0][s2i], oo[0][s2i], oo[1][s2i]);
        upk2(o2[1][s2i], oo[2][s2i], oo[3][s2i]);
    }
    float inv[4];
    #pragma unroll
    for (int ii = 0; ii < 4; ii++) inv[ii] = 1.f / l[ii];
    #pragma unroll
    for (int s2i = 0; s2i < 4; s2i++) {
        int c = 4 * tx + s2i;
        float4 w4 = make_float4(oo[0][s2i] * inv[0], oo[1][s2i] * inv[1],
                                oo[2][s2i] * inv[2], oo[3][s2i] * inv[3]);
        *(float4*)(O + c * HW + n0 + 4 * ty) = w4;
    }
}

// ---------------- 5. combine ----------------
__global__ void kcombine(const float* __restrict__ gamma, const float* __restrict__ alpha) {
    int i = blockIdx.x * 256 + threadIdx.x;
    g_outb[i] = gamma[0] * g_xout[i] + alpha[0] * g_gout[i];
}

// ---------------- 6. plain conv3x3: 4 oc per block ----------------
// grid (4, 16, B), block 256
__global__ void __launch_bounds__(256) kconv3(const float* __restrict__ w,
                                              const float* __restrict__ bias,
                                              int in_id, int out_id, int leaky_in) {
    const float* inb = pick_in(in_id);
    float* outb = pick_out(out_id);
    int b = blockIdx.z, ocg = blockIdx.y;

    __shared__ float ws[4 * 576];
    for (int i = threadIdx.x; i < 4 * 576; i += 256) {
        int o = i / 576, r = i % 576;
        ws[o * 576 + r] = w[(ocg * 4 + o) * 576 + r];
    }
    __syncthreads();

    int p = blockIdx.x * 1024 + threadIdx.x * 4;
    int row = p >> 6, col0 = p & 63;
    float acc[4][4];
    #pragma unroll
    for (int o = 0; o < 4; o++) {
        float bv = bias[ocg * 4 + o];
        #pragma unroll
        for (int u = 0; u < 4; u++) acc[o][u] = bv;
    }
    const float* in = inb + b * CH * HW;

    for (int ic = 0; ic < 64; ic++) {
        const float* ch = in + ic * HW;
        #pragma unroll
        for (int kh = 0; kh < 3; kh++) {
            int hh = row + kh - 1;
            if ((unsigned)hh >= 64u) continue;
            float v[6];
            #pragma unroll
            for (int u = 0; u < 6; u++) {
                int cc = col0 - 1 + u;
                float val = ((unsigned)cc < 64u) ? ch[hh * 64 + cc] : 0.f;
                if (leaky_in) val = val > 0.f ? val : 0.1f * val;
                v[u] = val;
            }
            #pragma unroll
            for (int o = 0; o < 4; o++) {
                const float* wr = &ws[o * 576 + ic * 9 + kh * 3];
                #pragma unroll
                for (int kw = 0; kw < 3; kw++) {
                    float wv = wr[kw];
                    acc[o][0] += wv * v[kw + 0];
                    acc[o][1] += wv * v[kw + 1];
                    acc[o][2] += wv * v[kw + 2];
                    acc[o][3] += wv * v[kw + 3];
                }
            }
        }
    }
    #pragma unroll
    for (int o = 0; o < 4; o++) {
        float* op = outb + (b * CH + ocg * 4 + o) * HW + p;
        float4 w4 = make_float4(acc[o][0], acc[o][1], acc[o][2], acc[o][3]);
        *(float4*)op = w4;
    }
}

// ---------------- 3b. 1x1 conv (shortcut path) ----------------
__global__ void k1x1(const float* __restrict__ w, const float* __restrict__ bias,
                     int in_id, int out_id) {
    const float* in = pick_in(in_id);
    float* out = pick_out(out_id);
    int b = blockIdx.z, og = blockIdx.y;
    int n0 = blockIdx.x * 128;

    __shared__ float si[64 * 128];
    __shared__ float sw[8 * 64];
    for (int i = threadIdx.x; i < 64 * 128; i += 128) {
        int c = i >> 7, px = i & 127;
        si[i] = in[(b * CH + c) * HW + n0 + px];
    }
    for (int i = threadIdx.x; i < 512; i += 128)
        sw[i] = w[(og * 8 + (i >> 6)) * 64 + (i & 63)];
    __syncthreads();

    float acc[8];
    #pragma unroll
    for (int o = 0; o < 8; o++) acc[o] = bias[og * 8 + o];
    for (int c = 0; c < 64; c++) {
        float iv = si[c * 128 + threadIdx.x];
        #pragma unroll
        for (int o = 0; o < 8; o++) acc[o] += sw[o * 64 + c] * iv;
    }
    #pragma unroll
    for (int o = 0; o < 8; o++)
        out[(b * CH + og * 8 + o) * HW + n0 + threadIdx.x] = acc[o];
}

// ---------------- 7. final ----------------
__global__ void kfinal(float* __restrict__ dout) {
    int i = blockIdx.x * 256 + threadIdx.x;
    dout[i] = g_t2[i] + g_sc[i] * g_gout[i];
}

extern "C" void kernel_launch(void* const* d_in, const int* in_sizes, int n_in,
                              void* d_out, int out_size) {
    const float* x       = (const float*)d_in[0];
    const float* guide   = (const float*)d_in[1];
    const float* lin_w   = (const float*)d_in[2];
    const float* lin_b   = (const float*)d_in[3];
    const float* coord_w = (const float*)d_in[4];
    const float* xq_w = (const float*)d_in[5];
    const float* xq_b = (const float*)d_in[6];
    const float* xk_w = (const float*)d_in[7];
    const float* xk_b = (const float*)d_in[8];
    const float* xv_w = (const float*)d_in[9];
    const float* xv_b = (const float*)d_in[10];
    const float* gq_w = (const float*)d_in[11];
    const float* gq_b = (const float*)d_in[12];
    const float* gk_w = (const float*)d_in[13];
    const float* gk_b = (const float*)d_in[14];
    const float* gamma = (const float*)d_in[15];
    const float* alpha = (const float*)d_in[16];
    const float* c1_w = (const float*)d_in[17];
    const float* c1_b = (const float*)d_in[18];
    const float* c2_w = (const float*)d_in[19];
    const float* c2_b = (const float*)d_in[20];
    const float* sc_w = (const float*)d_in[21];
    const float* sc_b = (const float*)d_in[22];
    float* out = (float*)d_out;

    cudaFuncSetAttribute(kflash, cudaFuncAttributeMaxDynamicSharedMemorySize, 66560);

    kstats<<<256, 256>>>(x, guide, lin_w, lin_b);
    kgated<<<dim3(4, 16, 4), 256>>>(x, guide, coord_w);

    kproj<<<dim3(32, 8, 4), 128>>>(xq_w, xq_b, xk_w, xk_b, xv_w, xv_b,
                                   gq_w, gq_b, gk_w, gk_b);

    kflash<<<dim3(64, BATCH, 2), 256, 66560>>>();

    kcombine<<<2048, 256>>>(gamma, alpha);

    kconv3<<<dim3(4, 16, BATCH), 256>>>(c1_w, c1_b, BUF_OUT, BUF_OT1, 1);
    kconv3<<<dim3(4, 16, BATCH), 256>>>(c2_w, c2_b, BUF_T1, BUF_OT2, 1);

    k1x1<<<dim3(32, 8, BATCH), 128>>>(sc_w, sc_b, BUF_OUT, BUF_SC);

    kfinal<<<2048, 256>>>(out);
}

// round 5
// speedup vs baseline: 2.7268x; 1.8273x over previous
#include <cuda_runtime.h>
#include <cuda_bf16.h>
#include <cstdint>

#define BATCH 2
#define CH 64
#define HW 4096   // 64*64

typedef unsigned long long u64;

__device__ __forceinline__ u64 pk2(float lo, float hi) {
    u64 r; asm("mov.b64 %0,{%1,%2};" : "=l"(r) : "f"(lo), "f"(hi)); return r;
}
__device__ __forceinline__ void upk2(u64 v, float& lo, float& hi) {
    asm("mov.b64 {%0,%1},%2;" : "=f"(lo), "=f"(hi) : "l"(v));
}
__device__ __forceinline__ u64 ffma2(u64 a, u64 b, u64 c) {
    u64 d; asm("fma.rn.f32x2 %0,%1,%2,%3;" : "=l"(d) : "l"(a), "l"(b), "l"(c)); return d;
}

// ---------------- scratch ----------------
__device__ float g_scale[4 * CH];
__device__ float g_xg[BATCH * CH * HW];
__device__ float g_gg[BATCH * CH * HW];
__device__ float g_xq[BATCH * CH * HW];
__device__ float g_xk[BATCH * CH * HW];
__device__ float g_xv[BATCH * CH * HW];
__device__ float g_gq[BATCH * CH * HW];
__device__ float g_gk[BATCH * CH * HW];
__device__ float g_xout[BATCH * CH * HW];
__device__ float g_gout[BATCH * CH * HW];
__device__ float g_outb[BATCH * CH * HW];
__device__ float g_t1[BATCH * CH * HW];
__device__ float g_t2[BATCH * CH * HW];
__device__ float g_sc[BATCH * CH * HW];

#define BUF_XG 0
#define BUF_GG 1
#define BUF_OUT 2
#define BUF_T1 3

#define BUF_XQ 0
#define BUF_XK 1
#define BUF_XV 2
#define BUF_GQ 3
#define BUF_GK 4
#define BUF_SC 5
#define BUF_OT1 6
#define BUF_OT2 7

__device__ __forceinline__ float* pick_in(int w) {
    switch (w) {
        case BUF_XG: return g_xg;
        case BUF_GG: return g_gg;
        case BUF_OUT: return g_outb;
        default:     return g_t1;
    }
}
__device__ __forceinline__ float* pick_out(int w) {
    switch (w) {
        case BUF_XQ: return g_xq;
        case BUF_XK: return g_xk;
        case BUF_XV: return g_xv;
        case BUF_GQ: return g_gq;
        case BUF_GK: return g_gk;
        case BUF_SC: return g_sc;
        case BUF_OT1: return g_t1;
        default:      return g_t2;
    }
}

// ================= mma.sync helpers (baseline PTX, works on plain sm_103) ==========
__device__ __forceinline__ uint32_t su32(const void* p) {
    uint32_t a;
    asm("{ .reg .u64 t; cvta.to.shared.u64 t, %1; cvt.u32.u64 %0, t; }" : "=r"(a) : "l"(p));
    return a;
}
__device__ __forceinline__ void mma_bf16(float* d, const uint32_t* a, uint32_t b0, uint32_t b1) {
    asm volatile(
        "mma.sync.aligned.m16n8k16.row.col.f32.bf16.bf16.f32 "
        "{%0,%1,%2,%3}, {%4,%5,%6,%7}, {%8,%9}, {%0,%1,%2,%3};"
        : "+f"(d[0]), "+f"(d[1]), "+f"(d[2]), "+f"(d[3])
        : "r"(a[0]), "r"(a[1]), "r"(a[2]), "r"(a[3]), "r"(b0), "r"(b1));
}
__device__ __forceinline__ void ldsm4(uint32_t* r, uint32_t addr) {
    asm volatile("ldmatrix.sync.aligned.m8n8.x4.shared.b16 {%0,%1,%2,%3}, [%4];"
                 : "=r"(r[0]), "=r"(r[1]), "=r"(r[2]), "=r"(r[3]) : "r"(addr));
}
__device__ __forceinline__ void ldsm4t(uint32_t* r, uint32_t addr) {
    asm volatile("ldmatrix.sync.aligned.m8n8.x4.trans.shared.b16 {%0,%1,%2,%3}, [%4];"
                 : "=r"(r[0]), "=r"(r[1]), "=r"(r[2]), "=r"(r[3]) : "r"(addr));
}
// pack (a,b) -> bf16x2 (a in low half)
__device__ __forceinline__ uint32_t cvt_bf2(float lo, float hi) {
    uint32_t r;
    asm("cvt.rn.bf16x2.f32 %0, %1, %2;" : "=r"(r) : "f"(hi), "f"(lo));
    return r;
}
// split pair (a,b) into bf16x2 hi word + bf16x2 residual word
__device__ __forceinline__ void split2(float a, float b, uint32_t& hw, uint32_t& lw) {
    uint32_t h = cvt_bf2(a, b);
    float ra = a - __uint_as_float(h << 16);
    float rb = b - __uint_as_float(h & 0xFFFF0000u);
    hw = h;
    lw = cvt_bf2(ra, rb);
}

// ---------------- 1. channel attention scalars ----------------
__global__ void kstats(const float* __restrict__ x, const float* __restrict__ g,
                       const float* __restrict__ lw, const float* __restrict__ lb) {
    int idx = blockIdx.x;
    int t = idx >> 7, b = (idx >> 6) & 1, c = idx & 63;
    const float* in = (t ? g : x) + (b * CH + c) * HW;
    float s = 0.f;
    for (int i = threadIdx.x; i < HW; i += 256) s += in[i];
    __shared__ float red[8];
    #pragma unroll
    for (int o = 16; o > 0; o >>= 1) s += __shfl_xor_sync(0xffffffffu, s, o);
    if ((threadIdx.x & 31) == 0) red[threadIdx.x >> 5] = s;
    __syncthreads();
    if (threadIdx.x == 0) {
        float tot = 0.f;
        #pragma unroll
        for (int i = 0; i < 8; i++) tot += red[i];
        float p = tot * (1.0f / (float)HW);
        float W = lw[0], B = lb[0];
        float h = p * W + B;
        h = h > 0.f ? h : 0.1f * h;
        float z = h * W + B;
        g_scale[idx] = 1.f / (1.f + expf(-z));
    }
}

// ---------------- 2. gated coord conv: 4 oc per block ----------------
__global__ void __launch_bounds__(256) kgated(const float* __restrict__ xin,
                                              const float* __restrict__ gin,
                                              const float* __restrict__ cw) {
    int z = blockIdx.z;
    int t = z >> 1, b = z & 1;
    const float* in = (t ? gin : xin) + b * CH * HW;
    float* out = (t ? g_gg : g_xg) + b * CH * HW;
    int ocg = blockIdx.y;

    __shared__ float ws[4 * 66 * 9];
    for (int i = threadIdx.x; i < 4 * 66 * 9; i += 256) {
        int o = i / 594, r = i % 594;
        ws[o * 594 + r] = cw[(ocg * 4 + o) * 594 + r];
    }
    __syncthreads();

    int p = blockIdx.x * 1024 + threadIdx.x * 4;
    int row = p >> 6, col0 = p & 63;
    float acc[4][4];
    #pragma unroll
    for (int o = 0; o < 4; o++)
        #pragma unroll
        for (int u = 0; u < 4; u++) acc[o][u] = 0.f;

    for (int ic = 0; ic < 64; ic++) {
        const float* ch = in + ic * HW;
        #pragma unroll
        for (int kh = 0; kh < 3; kh++) {
            int hh = row + kh - 1;
            if ((unsigned)hh >= 64u) continue;
            float v[6];
            #pragma unroll
            for (int u = 0; u < 6; u++) {
                int cc = col0 - 1 + u;
                v[u] = ((unsigned)cc < 64u) ? ch[hh * 64 + cc] : 0.f;
            }
            #pragma unroll
            for (int o = 0; o < 4; o++) {
                const float* wr = &ws[o * 594 + ic * 9 + kh * 3];
                #pragma unroll
                for (int kw = 0; kw < 3; kw++) {
                    float wv = wr[kw];
                    acc[o][0] += wv * v[kw + 0];
                    acc[o][1] += wv * v[kw + 1];
                    acc[o][2] += wv * v[kw + 2];
                    acc[o][3] += wv * v[kw + 3];
                }
            }
        }
    }
    #pragma unroll
    for (int ic = 64; ic < 66; ic++) {
        #pragma unroll
        for (int kh = 0; kh < 3; kh++) {
            int hh = row + kh - 1;
            if ((unsigned)hh >= 64u) continue;
            float yyv = (float)hh * (2.f / 63.f) - 1.f;
            float v[6];
            #pragma unroll
            for (int u = 0; u < 6; u++) {
                int cc = col0 - 1 + u;
                float val = 0.f;
                if ((unsigned)cc < 64u)
                    val = (ic == 64) ? ((float)cc * (2.f / 63.f) - 1.f) : yyv;
                v[u] = val;
            }
            #pragma unroll
            for (int o = 0; o < 4; o++) {
                const float* wr = &ws[o * 594 + ic * 9 + kh * 3];
                #pragma unroll
                for (int kw = 0; kw < 3; kw++) {
                    float wv = wr[kw];
                    acc[o][0] += wv * v[kw + 0];
                    acc[o][1] += wv * v[kw + 1];
                    acc[o][2] += wv * v[kw + 2];
                    acc[o][3] += wv * v[kw + 3];
                }
            }
        }
    }

    #pragma unroll
    for (int o = 0; o < 4; o++) {
        int oc = ocg * 4 + o;
        float s = g_scale[z * CH + oc];
        float* op = out + oc * HW + p;
        float4 w4 = make_float4(s * acc[o][0], s * acc[o][1], s * acc[o][2], s * acc[o][3]);
        *(float4*)op = w4;
    }
}

// ---------------- 3. fused QKV projections (f32x2) ----------------
__global__ void __launch_bounds__(128) kproj(
    const float* __restrict__ xq_w, const float* __restrict__ xq_b,
    const float* __restrict__ xk_w, const float* __restrict__ xk_b,
    const float* __restrict__ xv_w, const float* __restrict__ xv_b,
    const float* __restrict__ gq_w, const float* __restrict__ gq_b,
    const float* __restrict__ gk_w, const float* __restrict__ gk_b) {
    __shared__ float si[64 * 128];
    __shared__ float swt[3 * 512];
    __shared__ float sb2[3 * 8];

    int z = blockIdx.z;
    int side = z >> 1, b = z & 1;
    int og = blockIdx.y;
    int n0 = blockIdx.x * 128;
    int tid = threadIdx.x;

    const float* in = (side ? g_gg : g_xg) + b * CH * HW;
    const float* ws[3];
    const float* bs[3];
    float* outs[3];
    int nset;
    if (side == 0) {
        ws[0] = xq_w; ws[1] = xk_w; ws[2] = xv_w;
        bs[0] = xq_b; bs[1] = xk_b; bs[2] = xv_b;
        outs[0] = g_xq; outs[1] = g_xk; outs[2] = g_xv;
        nset = 3;
    } else {
        ws[0] = gq_w; ws[1] = gk_w; ws[2] = gk_w;
        bs[0] = gq_b; bs[1] = gk_b; bs[2] = gk_b;
        outs[0] = g_gq; outs[1] = g_gk; outs[2] = g_gk;
        nset = 2;
    }

    for (int i = tid; i < 2048; i += 128) {
        int c = i >> 5, p4 = (i & 31) * 4;
        *(float4*)(si + c * 128 + p4) = *(const float4*)(in + c * HW + n0 + p4);
    }
    for (int s = 0; s < nset; s++) {
        for (int i = tid; i < 512; i += 128) {
            int c = i >> 3, o = i & 7;
            swt[s * 512 + c * 8 + o] = ws[s][(og * 8 + o) * 64 + c];
        }
        if (tid < 8) sb2[s * 8 + tid] = bs[s][og * 8 + tid];
    }
    __syncthreads();

    u64 acc[3][4];
    #pragma unroll
    for (int s = 0; s < 3; s++)
        #pragma unroll
        for (int k = 0; k < 4; k++)
            acc[s][k] = pk2(sb2[s * 8 + 2 * k], sb2[s * 8 + 2 * k + 1]);

    if (side == 0) {
        for (int c = 0; c < 64; c++) {
            float iv = si[c * 128 + tid];
            u64 ivp = pk2(iv, iv);
            #pragma unroll
            for (int s = 0; s < 3; s++) {
                ulonglong2 wa = *(const ulonglong2*)(swt + s * 512 + c * 8);
                ulonglong2 wb = *(const ulonglong2*)(swt + s * 512 + c * 8 + 4);
                acc[s][0] = ffma2(ivp, wa.x, acc[s][0]);
                acc[s][1] = ffma2(ivp, wa.y, acc[s][1]);
                acc[s][2] = ffma2(ivp, wb.x, acc[s][2]);
                acc[s][3] = ffma2(ivp, wb.y, acc[s][3]);
            }
        }
    } else {
        for (int c = 0; c < 64; c++) {
            float iv = si[c * 128 + tid];
            u64 ivp = pk2(iv, iv);
            #pragma unroll
            for (int s = 0; s < 2; s++) {
                ulonglong2 wa = *(const ulonglong2*)(swt + s * 512 + c * 8);
                ulonglong2 wb = *(const ulonglong2*)(swt + s * 512 + c * 8 + 4);
                acc[s][0] = ffma2(ivp, wa.x, acc[s][0]);
                acc[s][1] = ffma2(ivp, wa.y, acc[s][1]);
                acc[s][2] = ffma2(ivp, wb.x, acc[s][2]);
                acc[s][3] = ffma2(ivp, wb.y, acc[s][3]);
            }
        }
    }

    for (int s = 0; s < nset; s++) {
        #pragma unroll
        for (int k = 0; k < 4; k++) {
            float lo, hi;
            upk2(acc[s][k], lo, hi);
            outs[s][(b * CH + og * 8 + 2 * k) * HW + n0 + tid] = lo;
            outs[s][(b * CH + og * 8 + 2 * k + 1) * HW + n0 + tid] = hi;
        }
    }
}

// ---------------- 4. flash attention via mma.sync (HMMA bf16, hi/lo split) ----------------
// grid (32, B, 2), block 256 = 8 warps. CTA: 128 Q-rows; warp: 16 rows. 64 KV tiles of 64.
// SMEM tiles padded to 72 bf16 per row (144B) -> conflict-free ldmatrix.
__global__ void __launch_bounds__(256, 1) kattn() {
    __shared__ __align__(16) uint8_t sraw[36864];

    const int tid = threadIdx.x;
    const int lane = tid & 31, wid = tid >> 5;
    const int tg = lane & 3, g = lane >> 2;
    const int b = blockIdx.y, kind = blockIdx.z;
    const int n0 = blockIdx.x * 128;
    const float* Qp = (kind ? g_gq : g_xq) + b * CH * HW;
    const float* Kp = (kind ? g_gk : g_xk) + b * CH * HW;
    const float* Vp = g_xv + b * CH * HW;
    float* Op = (kind ? g_gout : g_xout) + b * CH * HW;

    const uint32_t sb = su32(sraw);

    // ---- stage Q transposed [i][c] hi/lo, then ldmatrix A-frags (kept in regs) ----
    {
        __nv_bfloat16* Qh = (__nv_bfloat16*)sraw;            // [128][72]
        __nv_bfloat16* Ql = (__nv_bfloat16*)(sraw + 18432);
        for (int idx = tid; idx < 8192; idx += 256) {
            int c = idx >> 7, i = idx & 127;
            float a = Qp[c * HW + n0 + i];
            __nv_bfloat16 h = __float2bfloat16_rn(a);
            Qh[i * 72 + c] = h;
            Ql[i * 72 + c] = __float2bfloat16_rn(a - __bfloat162float(h));
        }
    }
    __syncthreads();

    uint32_t qh[4][4], ql[4][4];
    {
        int rl = lane & 15, ca = (lane >> 4) << 3;
        #pragma unroll
        for (int kc = 0; kc < 4; kc++) {
            uint32_t off = (uint32_t)(((16 * wid + rl) * 72 + 16 * kc + ca) * 2);
            ldsm4(qh[kc], sb + off);
            ldsm4(ql[kc], sb + 18432 + off);
        }
    }
    __syncthreads();

    float oacc[8][4];
    #pragma unroll
    for (int cb = 0; cb < 8; cb++) {
        oacc[cb][0] = 0.f; oacc[cb][1] = 0.f; oacc[cb][2] = 0.f; oacc[cb][3] = 0.f;
    }
    float mrow0 = -1e30f, mrow1 = -1e30f, lrow0 = 0.f, lrow1 = 0.f;

    // staging indices: thread -> (channel row, 16-wide j chunk)
    const int stc = tid >> 2;
    const int stj = (tid & 3) << 4;

    // per-lane ldmatrix byte offsets
    const uint32_t k_off = (uint32_t)(((lane & 15) * 72 + ((lane >> 4) << 3)) * 2);
    const uint32_t v_off = (uint32_t)(((((lane >> 4) << 3) + (lane & 7)) * 72 +
                                      (((lane >> 3) & 1) << 3)) * 2);

    for (int kt = 0; kt < 64; kt++) {
        int m0 = kt * 64;

        // ---- stage K/V tiles (hi/lo bf16), rows=channel, cols=j, stride 72 ----
        {
            const float* kp = Kp + stc * HW + m0 + stj;
            const float* vp = Vp + stc * HW + m0 + stj;
            uint32_t rowb = (uint32_t)(stc * 144 + stj * 2);
            #pragma unroll
            for (int u = 0; u < 4; u++) {
                float4 kx = *(const float4*)(kp + 4 * u);
                float4 vx = *(const float4*)(vp + 4 * u);
                uint32_t h0, l0, h1, l1;
                split2(kx.x, kx.y, h0, l0);
                split2(kx.z, kx.w, h1, l1);
                *(uint2*)(sraw + rowb + 8 * u)         = make_uint2(h0, h1);
                *(uint2*)(sraw + 9216 + rowb + 8 * u)  = make_uint2(l0, l1);
                split2(vx.x, vx.y, h0, l0);
                split2(vx.z, vx.w, h1, l1);
                *(uint2*)(sraw + 18432 + rowb + 8 * u) = make_uint2(h0, h1);
                *(uint2*)(sraw + 27648 + rowb + 8 * u) = make_uint2(l0, l1);
            }
        }
        __syncthreads();

        // ---- S = Q K^T (3 bf16 passes: qh*Kh + qh*Kl + ql*Kh) ----
        float sa[8][4];
        #pragma unroll
        for (int nb = 0; nb < 8; nb++) {
            sa[nb][0] = 0.f; sa[nb][1] = 0.f; sa[nb][2] = 0.f; sa[nb][3] = 0.f;
        }
        #pragma unroll
        for (int kc = 0; kc < 4; kc++) {
            #pragma unroll
            for (int jb = 0; jb < 4; jb++) {
                uint32_t bh[4], bl[4];
                uint32_t toff = (uint32_t)((kc * 16 * 72 + jb * 16) * 2);
                ldsm4t(bh, sb + k_off + toff);
                ldsm4t(bl, sb + 9216 + k_off + toff);
                mma_bf16(sa[2 * jb],     qh[kc], bh[0], bh[1]);
                mma_bf16(sa[2 * jb],     qh[kc], bl[0], bl[1]);
                mma_bf16(sa[2 * jb],     ql[kc], bh[0], bh[1]);
                mma_bf16(sa[2 * jb + 1], qh[kc], bh[2], bh[3]);
                mma_bf16(sa[2 * jb + 1], qh[kc], bl[2], bl[3]);
                mma_bf16(sa[2 * jb + 1], ql[kc], bh[2], bh[3]);
            }
        }

        // ---- online softmax: lane owns rows g (regs 0,1) and g+8 (regs 2,3) ----
        float tm0 = -1e30f, tm1 = -1e30f;
        #pragma unroll
        for (int nb = 0; nb < 8; nb++) {
            tm0 = fmaxf(tm0, fmaxf(sa[nb][0], sa[nb][1]));
            tm1 = fmaxf(tm1, fmaxf(sa[nb][2], sa[nb][3]));
        }
        tm0 = fmaxf(tm0, __shfl_xor_sync(0xffffffffu, tm0, 1));
        tm0 = fmaxf(tm0, __shfl_xor_sync(0xffffffffu, tm0, 2));
        tm1 = fmaxf(tm1, __shfl_xor_sync(0xffffffffu, tm1, 1));
        tm1 = fmaxf(tm1, __shfl_xor_sync(0xffffffffu, tm1, 2));
        float mn0 = fmaxf(mrow0, tm0), mn1 = fmaxf(mrow1, tm1);
        float corr0 = __expf(mrow0 - mn0), corr1 = __expf(mrow1 - mn1);
        mrow0 = mn0; mrow1 = mn1;

        float ps0 = 0.f, ps1 = 0.f;
        #pragma unroll
        for (int nb = 0; nb < 8; nb++) {
            sa[nb][0] = __expf(sa[nb][0] - mn0);
            sa[nb][1] = __expf(sa[nb][1] - mn0);
            sa[nb][2] = __expf(sa[nb][2] - mn1);
            sa[nb][3] = __expf(sa[nb][3] - mn1);
            ps0 += sa[nb][0] + sa[nb][1];
            ps1 += sa[nb][2] + sa[nb][3];
        }
        ps0 += __shfl_xor_sync(0xffffffffu, ps0, 1);
        ps0 += __shfl_xor_sync(0xffffffffu, ps0, 2);
        ps1 += __shfl_xor_sync(0xffffffffu, ps1, 1);
        ps1 += __shfl_xor_sync(0xffffffffu, ps1, 2);
        lrow0 = lrow0 * corr0 + ps0;
        lrow1 = lrow1 * corr1 + ps1;

        #pragma unroll
        for (int cb = 0; cb < 8; cb++) {
            oacc[cb][0] *= corr0; oacc[cb][1] *= corr0;
            oacc[cb][2] *= corr1; oacc[cb][3] *= corr1;
        }

        // ---- P a-frags straight from registers (hi/lo split) ----
        uint32_t ph[4][4], pl[4][4];
        #pragma unroll
        for (int kc = 0; kc < 4; kc++) {
            split2(sa[2 * kc][0],     sa[2 * kc][1],     ph[kc][0], pl[kc][0]);
            split2(sa[2 * kc][2],     sa[2 * kc][3],     ph[kc][1], pl[kc][1]);
            split2(sa[2 * kc + 1][0], sa[2 * kc + 1][1], ph[kc][2], pl[kc][2]);
            split2(sa[2 * kc + 1][2], sa[2 * kc + 1][3], ph[kc][3], pl[kc][3]);
        }

        // ---- O += P V^T (3 bf16 passes: ph*Vh + ph*Vl + pl*Vh) ----
        #pragma unroll
        for (int kc = 0; kc < 4; kc++) {
            #pragma unroll
            for (int cp = 0; cp < 4; cp++) {
                uint32_t bh[4], bl[4];
                uint32_t toff = (uint32_t)((cp * 16 * 72 + kc * 16) * 2);
                ldsm4(bh, sb + 18432 + v_off + toff);
                ldsm4(bl, sb + 27648 + v_off + toff);
                mma_bf16(oacc[2 * cp],     ph[kc], bh[0], bh[1]);
                mma_bf16(oacc[2 * cp],     ph[kc], bl[0], bl[1]);
                mma_bf16(oacc[2 * cp],     pl[kc], bh[0], bh[1]);
                mma_bf16(oacc[2 * cp + 1], ph[kc], bh[2], bh[3]);
                mma_bf16(oacc[2 * cp + 1], ph[kc], bl[2], bl[3]);
                mma_bf16(oacc[2 * cp + 1], pl[kc], bh[2], bh[3]);
            }
        }
        __syncthreads();
    }

    // ---- epilogue ----
    float inv0 = 1.f / lrow0, inv1 = 1.f / lrow1;
    int i0 = n0 + 16 * wid + g;
    #pragma unroll
    for (int cb = 0; cb < 8; cb++) {
        int c = 8 * cb + 2 * tg;
        Op[c * HW + i0]           = oacc[cb][0] * inv0;
        Op[(c + 1) * HW + i0]     = oacc[cb][1] * inv0;
        Op[c * HW + i0 + 8]       = oacc[cb][2] * inv1;
        Op[(c + 1) * HW + i0 + 8] = oacc[cb][3] * inv1;
    }
}

// ---------------- 5. combine ----------------
__global__ void kcombine(const float* __restrict__ gamma, const float* __restrict__ alpha) {
    int i = blockIdx.x * 256 + threadIdx.x;
    g_outb[i] = gamma[0] * g_xout[i] + alpha[0] * g_gout[i];
}

// ---------------- 6. plain conv3x3: 4 oc per block ----------------
__global__ void __launch_bounds__(256) kconv3(const float* __restrict__ w,
                                              const float* __restrict__ bias,
                                              int in_id, int out_id, int leaky_in) {
    const float* inb = pick_in(in_id);
    float* outb = pick_out(out_id);
    int b = blockIdx.z, ocg = blockIdx.y;

    __shared__ float ws[4 * 576];
    for (int i = threadIdx.x; i < 4 * 576; i += 256) {
        int o = i / 576, r = i % 576;
        ws[o * 576 + r] = w[(ocg * 4 + o) * 576 + r];
    }
    __syncthreads();

    int p = blockIdx.x * 1024 + threadIdx.x * 4;
    int row = p >> 6, col0 = p & 63;
    float acc[4][4];
    #pragma unroll
    for (int o = 0; o < 4; o++) {
        float bv = bias[ocg * 4 + o];
        #pragma unroll
        for (int u = 0; u < 4; u++) acc[o][u] = bv;
    }
    const float* in = inb + b * CH * HW;

    for (int ic = 0; ic < 64; ic++) {
        const float* ch = in + ic * HW;
        #pragma unroll
        for (int kh = 0; kh < 3; kh++) {
            int hh = row + kh - 1;
            if ((unsigned)hh >= 64u) continue;
            float v[6];
            #pragma unroll
            for (int u = 0; u < 6; u++) {
                int cc = col0 - 1 + u;
                float val = ((unsigned)cc < 64u) ? ch[hh * 64 + cc] : 0.f;
                if (leaky_in) val = val > 0.f ? val : 0.1f * val;
                v[u] = val;
            }
            #pragma unroll
            for (int o = 0; o < 4; o++) {
                const float* wr = &ws[o * 576 + ic * 9 + kh * 3];
                #pragma unroll
                for (int kw = 0; kw < 3; kw++) {
                    float wv = wr[kw];
                    acc[o][0] += wv * v[kw + 0];
                    acc[o][1] += wv * v[kw + 1];
                    acc[o][2] += wv * v[kw + 2];
                    acc[o][3] += wv * v[kw + 3];
                }
            }
        }
    }
    #pragma unroll
    for (int o = 0; o < 4; o++) {
        float* op = outb + (b * CH + ocg * 4 + o) * HW + p;
        float4 w4 = make_float4(acc[o][0], acc[o][1], acc[o][2], acc[o][3]);
        *(float4*)op = w4;
    }
}

// ---------------- 3b. 1x1 conv (shortcut path) ----------------
__global__ void k1x1(const float* __restrict__ w, const float* __restrict__ bias,
                     int in_id, int out_id) {
    const float* in = pick_in(in_id);
    float* out = pick_out(out_id);
    int b = blockIdx.z, og = blockIdx.y;
    int n0 = blockIdx.x * 128;

    __shared__ float si[64 * 128];
    __shared__ float sw[8 * 64];
    for (int i = threadIdx.x; i < 64 * 128; i += 128) {
        int c = i >> 7, px = i & 127;
        si[i] = in[(b * CH + c) * HW + n0 + px];
    }
    for (int i = threadIdx.x; i < 512; i += 128)
        sw[i] = w[(og * 8 + (i >> 6)) * 64 + (i & 63)];
    __syncthreads();

    float acc[8];
    #pragma unroll
    for (int o = 0; o < 8; o++) acc[o] = bias[og * 8 + o];
    for (int c = 0; c < 64; c++) {
        float iv = si[c * 128 + threadIdx.x];
        #pragma unroll
        for (int o = 0; o < 8; o++) acc[o] += sw[o * 64 + c] * iv;
    }
    #pragma unroll
    for (int o = 0; o < 8; o++)
        out[(b * CH + og * 8 + o) * HW + n0 + threadIdx.x] = acc[o];
}

// ---------------- 7. final ----------------
__global__ void kfinal(float* __restrict__ dout) {
    int i = blockIdx.x * 256 + threadIdx.x;
    dout[i] = g_t2[i] + g_sc[i] * g_gout[i];
}

extern "C" void kernel_launch(void* const* d_in, const int* in_sizes, int n_in,
                              void* d_out, int out_size) {
    const float* x       = (const float*)d_in[0];
    const float* guide   = (const float*)d_in[1];
    const float* lin_w   = (const float*)d_in[2];
    const float* lin_b   = (const float*)d_in[3];
    const float* coord_w = (const float*)d_in[4];
    const float* xq_w = (const float*)d_in[5];
    const float* xq_b = (const float*)d_in[6];
    const float* xk_w = (const float*)d_in[7];
    const float* xk_b = (const float*)d_in[8];
    const float* xv_w = (const float*)d_in[9];
    const float* xv_b = (const float*)d_in[10];
    const float* gq_w = (const float*)d_in[11];
    const float* gq_b = (const float*)d_in[12];
    const float* gk_w = (const float*)d_in[13];
    const float* gk_b = (const float*)d_in[14];
    const float* gamma = (const float*)d_in[15];
    const float* alpha = (const float*)d_in[16];
    const float* c1_w = (const float*)d_in[17];
    const float* c1_b = (const float*)d_in[18];
    const float* c2_w = (const float*)d_in[19];
    const float* c2_b = (const float*)d_in[20];
    const float* sc_w = (const float*)d_in[21];
    const float* sc_b = (const float*)d_in[22];
    float* out = (float*)d_out;

    kstats<<<256, 256>>>(x, guide, lin_w, lin_b);
    kgated<<<dim3(4, 16, 4), 256>>>(x, guide, coord_w);

    kproj<<<dim3(32, 8, 4), 128>>>(xq_w, xq_b, xk_w, xk_b, xv_w, xv_b,
                                   gq_w, gq_b, gk_w, gk_b);

    kattn<<<dim3(32, BATCH, 2), 256>>>();

    kcombine<<<2048, 256>>>(gamma, alpha);

    kconv3<<<dim3(4, 16, BATCH), 256>>>(c1_w, c1_b, BUF_OUT, BUF_OT1, 1);
    kconv3<<<dim3(4, 16, BATCH), 256>>>(c2_w, c2_b, BUF_T1, BUF_OT2, 1);

    k1x1<<<dim3(32, 8, BATCH), 128>>>(sc_w, sc_b, BUF_OUT, BUF_SC);

    kfinal<<<2048, 256>>>(out);
}